// round 12
// baseline (speedup 1.0000x reference)
#include <cuda_runtime.h>

#define L 2048
#define B 32
#define H 1024
#define H4 256
#define NB 148
#define NT 1024
#define NITEMS (B * (L / 2))   // 32768 items of (b, 2 l's)

// Scratch (allocation-free rule: __device__ globals)
__device__ float g_vpart[64][B][H];      // 8 MB partials (16 g each)
__device__ float g_vq[4][B][H];          // 512 KB quarter-reduced v
__device__ float g_v[B][H];              // 128 KB final v
__device__ float g_energy[B][L];         // 256 KB energies
__device__ unsigned g_maxu[B];           // monotone-encoded per-b max
__device__ unsigned g_bar;               // monotonic grid barrier counter
__device__ unsigned g_item;              // P3 warp work counter

__device__ __forceinline__ unsigned enc_f(float x) {
    unsigned u = __float_as_uint(x);
    return (x >= 0.f) ? (u | 0x80000000u) : ~u;
}
__device__ __forceinline__ float dec_f(unsigned e) {
    return (e & 0x80000000u) ? __uint_as_float(e ^ 0x80000000u)
                             : __uint_as_float(~e);
}

// Software grid barrier: monotonic counter, no reset across replays.
__device__ __forceinline__ void grid_sync() {
    __syncthreads();
    if (threadIdx.x == 0) {
        __threadfence();
        const unsigned old = atomicAdd(&g_bar, 1u);
        const unsigned tgt = (old / NB + 1u) * NB;
        while (*(volatile unsigned*)&g_bar < tgt) __nanosleep(64);
        __threadfence();
    }
    __syncthreads();
}

__global__ void __launch_bounds__(NT, 1)
fused_attn(const float* __restrict__ hidden,
           const float* __restrict__ enc,
           const float* __restrict__ W,
           const int*   __restrict__ lengths,
           float* __restrict__ out) {
    extern __shared__ float4 vsh4[];     // 128 KB: v for ALL b [B][H4]
    const int tid = threadIdx.x;
    const int bid = blockIdx.x;

    __shared__ float hsh[4][4][16];      // P1 hidden stage (1 KB)
    __shared__ float red_s[32];          // P4 reduction
    __shared__ int   sh_len[B];          // lengths cache

    if (bid == 0 && tid == 0) g_item = 0u;       // reset (pre-sync x3)
    if (bid == 0 && tid < B)  g_maxu[tid] = 0u;  // encoded -inf

    // ---------------- Phase 1: v partials ----------------
    // 512 groups = 64 g-slices x 8 b-quads; blocks 0..127, 4 groups each.
    if (bid < 128) {
        if (tid < 256) {   // stage hidden: 4 lg x 4 b x 16 g
            const int lg = tid >> 6, j = (tid >> 4) & 3, k = tid & 15;
            const int grp = bid * 4 + lg;
            const int gs = grp >> 3, bq = grp & 7;
            hsh[lg][j][k] = hidden[(size_t)(bq * 4 + j) * H + gs * 16 + k];
        }
        __syncthreads();

        const int lg = tid >> 8, hq = tid & 255;
        const int grp = bid * 4 + lg;
        const int gs = grp >> 3, bq = grp & 7;
        const int g0 = gs * 16, b0 = bq * 4;
        const float4* __restrict__ W4 = (const float4*)W;

        float4 acc[4];
        #pragma unroll
        for (int j = 0; j < 4; j++) acc[j] = make_float4(0.f, 0.f, 0.f, 0.f);

        #pragma unroll
        for (int r = 0; r < 4; r++) {
            float4 w[4];
            #pragma unroll
            for (int i = 0; i < 4; i++)
                w[i] = W4[(size_t)(g0 + r * 4 + i) * H4 + hq];
            #pragma unroll
            for (int i = 0; i < 4; i++) {
                #pragma unroll
                for (int j = 0; j < 4; j++) {
                    const float hv = hsh[lg][j][r * 4 + i];
                    acc[j].x += w[i].x * hv; acc[j].y += w[i].y * hv;
                    acc[j].z += w[i].z * hv; acc[j].w += w[i].w * hv;
                }
            }
        }
        #pragma unroll
        for (int j = 0; j < 4; j++)
            *(float4*)&g_vpart[gs][b0 + j][hq * 4] = acc[j];
    }
    grid_sync();

    // ---------------- Phase 2a: quarter reduce ----------------
    {
        const int t = bid * NT + tid;
        if (t < 32768) {
            const int q = t >> 13, f = t & 8191;
            const int b = f >> 8, h4 = f & 255;
            const int p0 = q * 16;
            float4 s = make_float4(0.f, 0.f, 0.f, 0.f);
            #pragma unroll
            for (int r = 0; r < 4; r++) {
                float4 v[4];
                #pragma unroll
                for (int i = 0; i < 4; i++)
                    v[i] = *(const float4*)&g_vpart[p0 + r * 4 + i][b][h4 * 4];
                #pragma unroll
                for (int i = 0; i < 4; i++) {
                    s.x += v[i].x; s.y += v[i].y; s.z += v[i].z; s.w += v[i].w;
                }
            }
            *(float4*)&g_vq[q][b][h4 * 4] = s;
        }
    }
    grid_sync();

    // ---------------- Phase 2b: final reduce -> g_v ----------------
    {
        const int t = bid * NT + tid;
        if (t < 8192) {
            const int b = t >> 8, h4 = t & 255;
            float4 v[4];
            #pragma unroll
            for (int q = 0; q < 4; q++)
                v[q] = *(const float4*)&g_vq[q][b][h4 * 4];
            float4 s = make_float4(v[0].x + v[1].x + v[2].x + v[3].x,
                                   v[0].y + v[1].y + v[2].y + v[3].y,
                                   v[0].z + v[1].z + v[2].z + v[3].z,
                                   v[0].w + v[1].w + v[2].w + v[3].w);
            *(float4*)&g_v[b][h4 * 4] = s;
        }
    }
    grid_sync();

    // ---------------- Phase 3: energies (warp-autonomous stealing) ----
    // vsh4 = all-b v (read-only after one sync). Items = (b, 2 l's) = 8 KB,
    // grabbed per-warp with prefetched atomic; rows l >= len[b] never read.
    {
        const float4* __restrict__ gv4 = (const float4*)g_v;
        for (int i = tid; i < B * H4; i += NT) vsh4[i] = gv4[i];
        if (tid < B) sh_len[tid] = lengths[tid];
        __syncthreads();

        const int lane = tid & 31;
        const float4* __restrict__ enc4 = (const float4*)enc;

        unsigned item;
        if (lane == 0) item = atomicAdd(&g_item, 1u);
        item = __shfl_sync(0xffffffffu, item, 0);

        while (item < NITEMS) {
            unsigned nxt;
            if (lane == 0) nxt = atomicAdd(&g_item, 1u);   // prefetch grab
            const int b  = item & 31;
            const int l0 = (int)(item >> 5) * 2;
            nxt = __shfl_sync(0xffffffffu, nxt, 0);

            const int len = sh_len[b];
            if (l0 < len) {
                const bool v1 = (l0 + 1 < len);
                const size_t ba = ((size_t)l0 * B + b) * H4;
                const size_t bb = ba + (size_t)B * H4;
                const float4* __restrict__ vb = vsh4 + b * H4;

                float a0 = 0.f, a1 = 0.f;
                if (v1) {
                    #pragma unroll
                    for (int k = 0; k < 8; k++) {
                        const float4 v  = vb[k * 32 + lane];
                        const float4 e0 = __ldcs(&enc4[ba + k * 32 + lane]);
                        const float4 e1 = __ldcs(&enc4[bb + k * 32 + lane]);
                        a0 += e0.x * v.x + e0.y * v.y + e0.z * v.z + e0.w * v.w;
                        a1 += e1.x * v.x + e1.y * v.y + e1.z * v.z + e1.w * v.w;
                    }
                } else {
                    #pragma unroll
                    for (int k = 0; k < 8; k++) {
                        const float4 v  = vb[k * 32 + lane];
                        const float4 e0 = __ldcs(&enc4[ba + k * 32 + lane]);
                        a0 += e0.x * v.x + e0.y * v.y + e0.z * v.z + e0.w * v.w;
                    }
                }
                #pragma unroll
                for (int s = 16; s; s >>= 1) {
                    a0 += __shfl_down_sync(0xffffffffu, a0, s);
                    a1 += __shfl_down_sync(0xffffffffu, a1, s);
                }
                if (lane == 0) {
                    g_energy[b][l0] = a0;
                    float m = a0;
                    if (v1) { g_energy[b][l0 + 1] = a1; m = fmaxf(m, a1); }
                    atomicMax(&g_maxu[b], enc_f(m));
                }
            }
            item = nxt;
        }
    }
    grid_sync();

    // ---------------- Phase 4: masked softmax ----------------
    if (bid < B) {
        const int b   = bid;
        const int len = sh_len[b];
        const int l0  = tid * 2;

        const float2 e = ((const float2*)&g_energy[b][0])[tid];
        const float mx = dec_f(g_maxu[b]);

        float x0 = (l0 + 0 < len) ? expf(e.x - mx) : 0.f;
        float x1 = (l0 + 1 < len) ? expf(e.y - mx) : 0.f;

        float sum = x0 + x1;
        #pragma unroll
        for (int s = 16; s; s >>= 1)
            sum += __shfl_xor_sync(0xffffffffu, sum, s);
        if ((tid & 31) == 0) red_s[tid >> 5] = sum;
        __syncthreads();
        if (tid < 32) {
            float m = red_s[tid];
            #pragma unroll
            for (int s = 16; s; s >>= 1)
                m += __shfl_xor_sync(0xffffffffu, m, s);
            if (tid == 0) red_s[0] = m;
        }
        __syncthreads();
        const float inv = 1.f / red_s[0];

        float2 x = make_float2(x0 * inv, x1 * inv);
        ((float2*)(out + (size_t)b * L))[tid] = x;
    }
}

// ---------------------------------------------------------------------------
extern "C" void kernel_launch(void* const* d_in, const int* in_sizes, int n_in,
                              void* d_out, int out_size) {
    const float* hidden  = (const float*)d_in[0];   // [1,B,H]
    const float* enc     = (const float*)d_in[1];   // [L,B,H]
    const float* W       = (const float*)d_in[2];   // [H,H]
    // d_in[3] = bias — provably cancels in softmax, unused
    const int*   lengths = (const int*)d_in[4];     // [B]
    float* out = (float*)d_out;                     // [B,1,L]

    const int dsm = B * H4 * (int)sizeof(float4);   // 128 KB
    cudaFuncSetAttribute(fused_attn,
                         cudaFuncAttributeMaxDynamicSharedMemorySize, dsm);
    fused_attn<<<NB, NT, dsm>>>(hidden, enc, W, lengths, out);
}

// round 13
// speedup vs baseline: 1.2937x; 1.2937x over previous
#include <cuda_runtime.h>

#define L 2048
#define B 32
#define H 1024
#define H4 256
#define NB 148
#define NT 1024
#define NITEMS 1024   // 32 b x 32 tiles of 64 l

// Scratch (allocation-free rule: __device__ globals)
__device__ float g_vpart[64][B][H];      // 8 MB partials (16 g each)
__device__ float g_vq[4][B][H];          // 512 KB quarter-reduced v
__device__ float g_v[B][H];              // 128 KB final v
__device__ float g_energy[B][L];         // 256 KB energies
__device__ unsigned g_maxu[B];           // monotone-encoded per-b max
__device__ unsigned g_bar;               // monotonic grid barrier counter
__device__ unsigned g_item;              // P3 block work counter

__device__ __forceinline__ unsigned enc_f(float x) {
    unsigned u = __float_as_uint(x);
    return (x >= 0.f) ? (u | 0x80000000u) : ~u;
}
__device__ __forceinline__ float dec_f(unsigned e) {
    return (e & 0x80000000u) ? __uint_as_float(e ^ 0x80000000u)
                             : __uint_as_float(~e);
}

// Software grid barrier: monotonic counter, no reset across replays.
__device__ __forceinline__ void grid_sync() {
    __syncthreads();
    if (threadIdx.x == 0) {
        __threadfence();
        const unsigned old = atomicAdd(&g_bar, 1u);
        const unsigned tgt = (old / NB + 1u) * NB;
        while (*(volatile unsigned*)&g_bar < tgt) __nanosleep(64);
        __threadfence();
    }
    __syncthreads();
}

__global__ void __launch_bounds__(NT, 1)
fused_attn(const float* __restrict__ hidden,
           const float* __restrict__ enc,
           const float* __restrict__ W,
           const int*   __restrict__ lengths,
           float* __restrict__ out) {
    extern __shared__ float4 vsh4[];     // 128 KB: v for ALL b [B][H4]
    const int tid = threadIdx.x;
    const int bid = blockIdx.x;

    __shared__ float hsh[4][4][16];      // P1 hidden stage (1 KB)
    __shared__ float red_s[32];          // P4 reduction
    __shared__ int   sh_len[B];          // lengths cache
    __shared__ int   sh_item[2];         // double-buffered work broadcast

    if (bid == 0 && tid == 0) g_item = 0u;       // reset (pre-sync)
    if (bid == 0 && tid < B)  g_maxu[tid] = 0u;  // encoded -inf

    // ---------------- Phase 1: v partials ----------------
    // 512 groups = 64 g-slices x 8 b-quads; blocks 0..127, 4 groups each.
    if (bid < 128) {
        if (tid < 256) {   // stage hidden: 4 lg x 4 b x 16 g
            const int lg = tid >> 6, j = (tid >> 4) & 3, k = tid & 15;
            const int grp = bid * 4 + lg;
            const int gs = grp >> 3, bq = grp & 7;
            hsh[lg][j][k] = hidden[(size_t)(bq * 4 + j) * H + gs * 16 + k];
        }
        __syncthreads();

        const int lg = tid >> 8, hq = tid & 255;
        const int grp = bid * 4 + lg;
        const int gs = grp >> 3, bq = grp & 7;
        const int g0 = gs * 16, b0 = bq * 4;
        const float4* __restrict__ W4 = (const float4*)W;

        float4 acc[4];
        #pragma unroll
        for (int j = 0; j < 4; j++) acc[j] = make_float4(0.f, 0.f, 0.f, 0.f);

        #pragma unroll
        for (int r = 0; r < 4; r++) {
            float4 w[4];
            #pragma unroll
            for (int i = 0; i < 4; i++)
                w[i] = W4[(size_t)(g0 + r * 4 + i) * H4 + hq];
            #pragma unroll
            for (int i = 0; i < 4; i++) {
                #pragma unroll
                for (int j = 0; j < 4; j++) {
                    const float hv = hsh[lg][j][r * 4 + i];
                    acc[j].x += w[i].x * hv; acc[j].y += w[i].y * hv;
                    acc[j].z += w[i].z * hv; acc[j].w += w[i].w * hv;
                }
            }
        }
        #pragma unroll
        for (int j = 0; j < 4; j++)
            *(float4*)&g_vpart[gs][b0 + j][hq * 4] = acc[j];
    }
    grid_sync();

    // ---------------- Phase 2a: quarter reduce ----------------
    {
        const int t = bid * NT + tid;
        if (t < 32768) {
            const int q = t >> 13, f = t & 8191;
            const int b = f >> 8, h4 = f & 255;
            const int p0 = q * 16;
            float4 s = make_float4(0.f, 0.f, 0.f, 0.f);
            #pragma unroll
            for (int r = 0; r < 4; r++) {
                float4 v[4];
                #pragma unroll
                for (int i = 0; i < 4; i++)
                    v[i] = *(const float4*)&g_vpart[p0 + r * 4 + i][b][h4 * 4];
                #pragma unroll
                for (int i = 0; i < 4; i++) {
                    s.x += v[i].x; s.y += v[i].y; s.z += v[i].z; s.w += v[i].w;
                }
            }
            *(float4*)&g_vq[q][b][h4 * 4] = s;
        }
    }
    grid_sync();

    // ---------------- Phase 2b: final reduce -> g_v ----------------
    {
        const int t = bid * NT + tid;
        if (t < 8192) {
            const int b = t >> 8, h4 = t & 255;
            float4 v[4];
            #pragma unroll
            for (int q = 0; q < 4; q++)
                v[q] = *(const float4*)&g_vq[q][b][h4 * 4];
            float4 s = make_float4(v[0].x + v[1].x + v[2].x + v[3].x,
                                   v[0].y + v[1].y + v[2].y + v[3].y,
                                   v[0].z + v[1].z + v[2].z + v[3].z,
                                   v[0].w + v[1].w + v[2].w + v[3].w);
            *(float4*)&g_v[b][h4 * 4] = s;
        }
    }
    grid_sync();

    // ---------------- Phase 3: energies (block stealing, v in smem) ----
    // All-b v preloaded once (read-only). Items = (b, 64-l tile), block-level
    // dynamic grabs (1024 atomics total). One sync per item via double-
    // buffered sh_item (slot i rewritten only at i+2, after the i+1 barrier).
    // Rows l >= len[b] never read: exact (masked to 0 downstream).
    {
        const float4* __restrict__ gv4 = (const float4*)g_v;
        for (int i = tid; i < B * H4; i += NT) vsh4[i] = gv4[i];
        if (tid < B) sh_len[tid] = lengths[tid];

        const int warp = tid >> 5, lane = tid & 31;
        const float4* __restrict__ enc4 = (const float4*)enc;

        int it = 0;
        for (;;) {
            if (tid == 0) sh_item[it & 1] = (int)atomicAdd(&g_item, 1u);
            __syncthreads();
            const int item = sh_item[it & 1];
            it++;
            if (item >= NITEMS) break;

            const int b   = item >> 5;
            const int len = sh_len[b];
            const int l0  = (item & 31) * 64;
            if (l0 >= len) continue;          // block-uniform: safe skip

            const int la = l0 + warp * 2;     // 2 l's per warp
            if (la >= len) continue;          // warp-uniform tail skip
            const bool v1 = (la + 1 < len);

            const size_t ba = ((size_t)la * B + b) * H4;
            const size_t bb = ba + (size_t)B * H4;
            const float4* __restrict__ vb = vsh4 + b * H4;

            float a0 = 0.f, a1 = 0.f;
            if (v1) {
                #pragma unroll
                for (int k = 0; k < 8; k++) {
                    const float4 v  = vb[k * 32 + lane];
                    const float4 e0 = __ldcs(&enc4[ba + k * 32 + lane]);
                    const float4 e1 = __ldcs(&enc4[bb + k * 32 + lane]);
                    a0 += e0.x * v.x + e0.y * v.y + e0.z * v.z + e0.w * v.w;
                    a1 += e1.x * v.x + e1.y * v.y + e1.z * v.z + e1.w * v.w;
                }
            } else {
                #pragma unroll
                for (int k = 0; k < 8; k++) {
                    const float4 v  = vb[k * 32 + lane];
                    const float4 e0 = __ldcs(&enc4[ba + k * 32 + lane]);
                    a0 += e0.x * v.x + e0.y * v.y + e0.z * v.z + e0.w * v.w;
                }
            }
            #pragma unroll
            for (int s = 16; s; s >>= 1) {
                a0 += __shfl_down_sync(0xffffffffu, a0, s);
                a1 += __shfl_down_sync(0xffffffffu, a1, s);
            }
            if (lane == 0) {
                g_energy[b][la] = a0;
                float m = a0;
                if (v1) { g_energy[b][la + 1] = a1; m = fmaxf(m, a1); }
                atomicMax(&g_maxu[b], enc_f(m));   // max over valid only
            }
        }
    }
    grid_sync();

    // ---------------- Phase 4: masked softmax ----------------
    if (bid < B) {
        const int b   = bid;
        const int len = sh_len[b];
        const int l0  = tid * 2;

        const float2 e = ((const float2*)&g_energy[b][0])[tid];
        const float mx = dec_f(g_maxu[b]);

        float x0 = (l0 + 0 < len) ? expf(e.x - mx) : 0.f;
        float x1 = (l0 + 1 < len) ? expf(e.y - mx) : 0.f;

        float sum = x0 + x1;
        #pragma unroll
        for (int s = 16; s; s >>= 1)
            sum += __shfl_xor_sync(0xffffffffu, sum, s);
        if ((tid & 31) == 0) red_s[tid >> 5] = sum;
        __syncthreads();
        if (tid < 32) {
            float m = red_s[tid];
            #pragma unroll
            for (int s = 16; s; s >>= 1)
                m += __shfl_xor_sync(0xffffffffu, m, s);
            if (tid == 0) red_s[0] = m;
        }
        __syncthreads();
        const float inv = 1.f / red_s[0];

        float2 x = make_float2(x0 * inv, x1 * inv);
        ((float2*)(out + (size_t)b * L))[tid] = x;
    }
}

// ---------------------------------------------------------------------------
extern "C" void kernel_launch(void* const* d_in, const int* in_sizes, int n_in,
                              void* d_out, int out_size) {
    const float* hidden  = (const float*)d_in[0];   // [1,B,H]
    const float* enc     = (const float*)d_in[1];   // [L,B,H]
    const float* W       = (const float*)d_in[2];   // [H,H]
    // d_in[3] = bias — provably cancels in softmax, unused
    const int*   lengths = (const int*)d_in[4];     // [B]
    float* out = (float*)d_out;                     // [B,1,L]

    const int dsm = B * H4 * (int)sizeof(float4);   // 128 KB
    cudaFuncSetAttribute(fused_attn,
                         cudaFuncAttributeMaxDynamicSharedMemorySize, dsm);
    fused_attn<<<NB, NT, dsm>>>(hidden, enc, W, lengths, out);
}